// round 5
// baseline (speedup 1.0000x reference)
#include <cuda_runtime.h>
#include <math.h>
#include <stdint.h>

#define N_NODES 24576
#define B_GRAPHS 128
#define D_IN     92
#define DMODEL   512
#define NHEAD    8
#define HDIM     64
#define NLAYER   3
#define DFF      2048

// ---------------- device scratch ----------------
__device__ float g_h   [(size_t)N_NODES * DMODEL];
__device__ float g_qkv [(size_t)N_NODES * 3 * DMODEL];
__device__ float g_o   [(size_t)N_NODES * DMODEL];
__device__ float g_x   [(size_t)N_NODES * DMODEL];
__device__ float g_f   [(size_t)N_NODES * DFF];
__device__ float g_pool[B_GRAPHS * DMODEL];
__device__ float g_ph  [B_GRAPHS * DMODEL];
__device__ int   g_counts[B_GRAPHS];
__device__ int   g_starts[B_GRAPHS];

// ---------------- graph metadata ----------------
__global__ void count_kernel(const int* __restrict__ batch) {
    int i = blockIdx.x * blockDim.x + threadIdx.x;
    if (i < N_NODES) {
        int g = batch[i];
        if (g >= 0 && g < B_GRAPHS) atomicAdd(&g_counts[g], 1);
    }
}

__global__ void scan_kernel() {
    int s = 0;
    for (int g = 0; g < B_GRAPHS; g++) {
        g_starts[g] = s;
        s += g_counts[g];
    }
}

// ---------------- tf32 helpers ----------------
__device__ __forceinline__ uint32_t f2tf(float x) {
    uint32_t y;
    asm("cvt.rna.tf32.f32 %0, %1;" : "=r"(y) : "f"(x));
    return y;
}

__device__ __forceinline__ void mma_tf32(float d[4], const uint32_t* a, const uint32_t* b) {
    asm volatile(
        "mma.sync.aligned.m16n8k8.row.col.f32.tf32.tf32.f32 "
        "{%0,%1,%2,%3}, {%4,%5,%6,%7}, {%8,%9}, {%0,%1,%2,%3};\n"
        : "+f"(d[0]), "+f"(d[1]), "+f"(d[2]), "+f"(d[3])
        : "r"(a[0]), "r"(a[1]), "r"(a[2]), "r"(a[3]),
          "r"(b[0]), "r"(b[1]));
}

// ---------------- TF32 GEMM v2:  C = A @ W^T + bias (+res) (+act) ----------------
// 128x256 block tile, BK=16, 8 warps (2m x 4n), 64x64 warp tile,
// fragment-ordered smem (A: 4-word tuples -> LDS.128, B: 2-word -> LDS.64).
// M % 128 == 0, N % 256 == 0, K % 4 == 0. ACT: 0 none, 1 relu, 2 silu.
#define GBM 128
#define GBN 256
#define GBK 16

template <int ACT>
__global__ void __launch_bounds__(256)
tgemm2_kernel(const float* __restrict__ A, const float* __restrict__ W,
              const float* __restrict__ bias, const float* __restrict__ res,
              float* __restrict__ C, int M, int N, int K)
{
    // A frag store: [buf][(mt*2+ks)*128 + lane*4 + w], mt 0..7  -> 2048 u32 = 8KB/buf
    // B frag store: [buf][(nt*2+ks)*64  + lane*2 + w], nt 0..31 -> 4096 u32 = 16KB/buf
    __shared__ uint32_t As[2][2048];
    __shared__ uint32_t Bs[2][4096];

    const int tid  = threadIdx.x;
    const int lane = tid & 31;
    const int wid  = tid >> 5;
    const int mw   = wid >> 2;     // 0..1
    const int nw   = wid & 3;      // 0..3
    const int bm = blockIdx.y * GBM;
    const int bn = blockIdx.x * GBN;
    const int fr = lane >> 2;      // 0..7
    const int fc = lane & 3;       // 0..3

    float acc[4][8][4];
#pragma unroll
    for (int a = 0; a < 4; a++)
#pragma unroll
        for (int b = 0; b < 8; b++)
#pragma unroll
            for (int c = 0; c < 4; c++) acc[a][b][c] = 0.f;

    const int ntiles = (K + GBK - 1) / GBK;

    uint4 pa[2], pb[4];

    auto ldg4 = [&](const float* __restrict__ P, int row, int k, uint4& o4) {
        if (k + 4 <= K) {
            float4 f = *(const float4*)(P + (size_t)row * K + k);
            o4.x = f2tf(f.x); o4.y = f2tf(f.y); o4.z = f2tf(f.z); o4.w = f2tf(f.w);
        } else {
            o4 = make_uint4(0u, 0u, 0u, 0u);
        }
    };

    auto fetch = [&](int t) {
#pragma unroll
        for (int i = 0; i < 2; i++) {
            int idx = tid + 256 * i;
            int r = idx >> 2, c4 = (idx & 3) * 4;
            ldg4(A, bm + r, t * GBK + c4, pa[i]);
        }
#pragma unroll
        for (int i = 0; i < 4; i++) {
            int idx = tid + 256 * i;
            int r = idx >> 2, c4 = (idx & 3) * 4;
            ldg4(W, bn + r, t * GBK + c4, pb[i]);
        }
    };

    auto stage = [&](int buf) {
#pragma unroll
        for (int i = 0; i < 2; i++) {
            int idx = tid + 256 * i;
            int r = idx >> 2, c4 = (idx & 3) * 4;
            int mt = r >> 4, h = (r >> 3) & 1, fra = r & 7;
            int ks = c4 >> 3, half = (c4 >> 2) & 1;
            int base = ((mt * 2 + ks) * 32 + fra * 4) * 4 + half * 2 + h;
            As[buf][base +  0] = pa[i].x;
            As[buf][base +  4] = pa[i].y;
            As[buf][base +  8] = pa[i].z;
            As[buf][base + 12] = pa[i].w;
        }
#pragma unroll
        for (int i = 0; i < 4; i++) {
            int idx = tid + 256 * i;
            int r = idx >> 2, c4 = (idx & 3) * 4;
            int nt = r >> 3, frb = r & 7;
            int ks = c4 >> 3, half = (c4 >> 2) & 1;
            int base = ((nt * 2 + ks) * 32 + frb * 4) * 2 + half;
            Bs[buf][base + 0] = pb[i].x;
            Bs[buf][base + 2] = pb[i].y;
            Bs[buf][base + 4] = pb[i].z;
            Bs[buf][base + 6] = pb[i].w;
        }
    };

    fetch(0);
    stage(0);
    __syncthreads();

    for (int t = 0; t < ntiles; t++) {
        int buf = t & 1;
        if (t + 1 < ntiles) fetch(t + 1);
#pragma unroll
        for (int ks = 0; ks < 2; ks++) {
            uint4 af[4];
            uint2 bf[8];
#pragma unroll
            for (int mt = 0; mt < 4; mt++)
                af[mt] = *(const uint4*)&As[buf][((mw * 4 + mt) * 2 + ks) * 128 + lane * 4];
#pragma unroll
            for (int nt = 0; nt < 8; nt++)
                bf[nt] = *(const uint2*)&Bs[buf][((nw * 8 + nt) * 2 + ks) * 64 + lane * 2];
#pragma unroll
            for (int mt = 0; mt < 4; mt++)
#pragma unroll
                for (int nt = 0; nt < 8; nt++)
                    mma_tf32(acc[mt][nt], &af[mt].x, &bf[nt].x);
        }
        if (t + 1 < ntiles) {
            stage(buf ^ 1);
            __syncthreads();
        }
    }

    // epilogue
    const int wmBase = bm + mw * 64;
    const int wnBase = bn + nw * 64;
#pragma unroll
    for (int mt = 0; mt < 4; mt++) {
#pragma unroll
        for (int nt = 0; nt < 8; nt++) {
            int col = wnBase + nt * 8 + 2 * fc;
            float2 bi = *(const float2*)(bias + col);
#pragma unroll
            for (int h = 0; h < 2; h++) {
                int row = wmBase + mt * 16 + fr + h * 8;
                float v0 = acc[mt][nt][h * 2 + 0] + bi.x;
                float v1 = acc[mt][nt][h * 2 + 1] + bi.y;
                if (res) {
                    float2 rr = *(const float2*)(res + (size_t)row * N + col);
                    v0 += rr.x; v1 += rr.y;
                }
                if (ACT == 1) { v0 = fmaxf(v0, 0.f); v1 = fmaxf(v1, 0.f); }
                if (ACT == 2) { v0 = v0 / (1.f + expf(-v0)); v1 = v1 / (1.f + expf(-v1)); }
                *(float2*)(C + (size_t)row * N + col) = make_float2(v0, v1);
            }
        }
    }
}

// ---------------- attention v3: block per (graph, head), 32 queries/stage ----------------
__global__ void __launch_bounds__(256)
attn3_kernel(const float* __restrict__ qkv, float* __restrict__ o)
{
    __shared__ float Ks[32][65];
    __shared__ float Vs[32][64];
    __shared__ float qs[32][64];

    const int g = blockIdx.x, head = blockIdx.y;
    const int s0 = g_starts[g], cnt = g_counts[g];
    const int tid = threadIdx.x, lane = tid & 31, wid = tid >> 5;
    const float scale = 0.125f;   // 1/sqrt(64)

    for (int qg = 0; qg < cnt; qg += 32) {
        int nq = min(32, cnt - qg);
        __syncthreads();
        // stage up to 32 query rows (pre-scaled)
        for (int i = tid; i < nq * 16; i += 256) {
            int r = i >> 4, c = (i & 15) * 4;
            const float* qr = qkv + (size_t)(s0 + qg + r) * (3 * DMODEL) + head * HDIM;
            float4 qf = *(const float4*)(qr + c);
            qs[r][c]     = qf.x * scale;
            qs[r][c + 1] = qf.y * scale;
            qs[r][c + 2] = qf.z * scale;
            qs[r][c + 3] = qf.w * scale;
        }
        __syncthreads();

        // per-warp: 4 query states (queries wid + 8*j)
        float m[4], l[4], a0[4], a1[4];
#pragma unroll
        for (int j = 0; j < 4; j++) { m[j] = -1e30f; l[j] = 0.f; a0[j] = 0.f; a1[j] = 0.f; }

        for (int t0 = 0; t0 < cnt; t0 += 32) {
            int nk = min(32, cnt - t0);
            __syncthreads();
            for (int i = tid; i < nk * 16; i += 256) {
                int r = i >> 4, c = (i & 15) * 4;
                const float* kr = qkv + (size_t)(s0 + t0 + r) * (3 * DMODEL) + DMODEL + head * HDIM;
                float4 kf = *(const float4*)(kr + c);
                float4 vf = *(const float4*)(kr + DMODEL + c);
                Ks[r][c] = kf.x; Ks[r][c + 1] = kf.y; Ks[r][c + 2] = kf.z; Ks[r][c + 3] = kf.w;
                *(float4*)&Vs[r][c] = vf;
            }
            __syncthreads();

#pragma unroll
            for (int j = 0; j < 4; j++) {
                int qi = wid + 8 * j;
                if (qi >= nq) break;
                float s = -1e30f;
                if (lane < nk) {
                    float p0 = 0.f, p1 = 0.f, p2 = 0.f, p3 = 0.f;
#pragma unroll 8
                    for (int d = 0; d < 64; d += 4) {
                        p0 += qs[qi][d]     * Ks[lane][d];
                        p1 += qs[qi][d + 1] * Ks[lane][d + 1];
                        p2 += qs[qi][d + 2] * Ks[lane][d + 2];
                        p3 += qs[qi][d + 3] * Ks[lane][d + 3];
                    }
                    s = (p0 + p1) + (p2 + p3);
                }
                float tm = s;
#pragma unroll
                for (int off = 16; off; off >>= 1)
                    tm = fmaxf(tm, __shfl_xor_sync(0xffffffffu, tm, off));
                float nm = fmaxf(m[j], tm);
                float corr = expf(m[j] - nm);
                float e = (lane < nk) ? expf(s - nm) : 0.f;
                float es = e;
#pragma unroll
                for (int off = 16; off; off >>= 1)
                    es += __shfl_xor_sync(0xffffffffu, es, off);
                l[j] = l[j] * corr + es;
                a0[j] *= corr; a1[j] *= corr;
                for (int kk = 0; kk < nk; kk++) {
                    float w = __shfl_sync(0xffffffffu, e, kk);
                    a0[j] += w * Vs[kk][lane];
                    a1[j] += w * Vs[kk][lane + 32];
                }
                m[j] = nm;
            }
        }

#pragma unroll
        for (int j = 0; j < 4; j++) {
            int qi = wid + 8 * j;
            if (qi >= nq) break;
            float inv = 1.f / l[j];
            float* orow = o + (size_t)(s0 + qg + qi) * DMODEL + head * HDIM;
            orow[lane]      = a0[j] * inv;
            orow[lane + 32] = a1[j] * inv;
        }
    }
}

// ---------------- layernorm (in-place), one warp per row ----------------
__global__ void ln_kernel(float* __restrict__ x,
                          const float* __restrict__ gamma,
                          const float* __restrict__ beta)
{
    int row  = (blockIdx.x * blockDim.x + threadIdx.x) >> 5;
    int lane = threadIdx.x & 31;
    if (row >= N_NODES) return;
    float* xr = x + (size_t)row * DMODEL;

    float v[16];
    float s = 0.f;
#pragma unroll
    for (int i = 0; i < 16; i++) { v[i] = xr[i * 32 + lane]; s += v[i]; }
#pragma unroll
    for (int off = 16; off; off >>= 1) s += __shfl_xor_sync(0xffffffffu, s, off);
    float mu = s * (1.f / DMODEL);

    float s2 = 0.f;
#pragma unroll
    for (int i = 0; i < 16; i++) { float d = v[i] - mu; v[i] = d; s2 += d * d; }
#pragma unroll
    for (int off = 16; off; off >>= 1) s2 += __shfl_xor_sync(0xffffffffu, s2, off);
    float rstd = rsqrtf(s2 * (1.f / DMODEL) + 1e-5f);

#pragma unroll
    for (int i = 0; i < 16; i++) {
        int c = i * 32 + lane;
        xr[c] = v[i] * rstd * gamma[c] + beta[c];
    }
}

// ---------------- segment mean pool ----------------
__global__ void pool_kernel(const float* __restrict__ h, float* __restrict__ pooled)
{
    int g = blockIdx.x;
    int d = threadIdx.x;   // 512 threads
    int s0 = g_starts[g];
    int c  = g_counts[g];
    float acc = 0.f;
    for (int j = 0; j < c; j++) acc += h[(size_t)(s0 + j) * DMODEL + d];
    pooled[g * DMODEL + d] = (c > 0) ? acc / (float)c : 0.f;
}

// ---------------- final head ----------------
__global__ void head2_kernel(const float* __restrict__ ph,
                             const float* __restrict__ w2,
                             const float* __restrict__ b2,
                             float* __restrict__ out)
{
    int g = blockIdx.x;
    int lane = threadIdx.x;
    float acc = 0.f;
    for (int i = lane; i < DMODEL; i += 32) acc += ph[g * DMODEL + i] * w2[i];
#pragma unroll
    for (int off = 16; off; off >>= 1) acc += __shfl_xor_sync(0xffffffffu, acc, off);
    if (lane == 0) out[g] = acc + b2[0];
}

// ---------------- host orchestration ----------------
extern "C" void kernel_launch(void* const* d_in, const int* in_sizes, int n_in,
                              void* d_out, int out_size)
{
    const float* node_features = (const float*)d_in[0];
    const int*   batch         = (const int*)  d_in[3];
    const float* emb_w   = (const float*)d_in[4];
    const float* emb_b   = (const float*)d_in[5];
    const float* in_proj_w = (const float*)d_in[6];
    const float* in_proj_b = (const float*)d_in[7];
    const float* out_w   = (const float*)d_in[8];
    const float* out_b   = (const float*)d_in[9];
    const float* ln1_g   = (const float*)d_in[10];
    const float* ln1_b   = (const float*)d_in[11];
    const float* ffn_w1  = (const float*)d_in[12];
    const float* ffn_b1  = (const float*)d_in[13];
    const float* ffn_w2  = (const float*)d_in[14];
    const float* ffn_b2  = (const float*)d_in[15];
    const float* ln2_g   = (const float*)d_in[16];
    const float* ln2_b   = (const float*)d_in[17];
    const float* head_w1 = (const float*)d_in[18];
    const float* head_b1 = (const float*)d_in[19];
    const float* head_w2 = (const float*)d_in[20];
    const float* head_b2 = (const float*)d_in[21];
    float* out = (float*)d_out;

    float *ph, *pqkv, *po, *px, *pf, *ppool, *pph;
    int *pcounts;
    cudaGetSymbolAddress((void**)&ph,     g_h);
    cudaGetSymbolAddress((void**)&pqkv,   g_qkv);
    cudaGetSymbolAddress((void**)&po,     g_o);
    cudaGetSymbolAddress((void**)&px,     g_x);
    cudaGetSymbolAddress((void**)&pf,     g_f);
    cudaGetSymbolAddress((void**)&ppool,  g_pool);
    cudaGetSymbolAddress((void**)&pph,    g_ph);
    cudaGetSymbolAddress((void**)&pcounts, g_counts);

    // graph metadata
    cudaMemsetAsync(pcounts, 0, B_GRAPHS * sizeof(int));
    count_kernel<<<(N_NODES + 255) / 256, 256>>>(batch);
    scan_kernel<<<1, 1>>>();

    // embedding: h = X @ emb_w^T + emb_b
    tgemm2_kernel<0><<<dim3(DMODEL / GBN, N_NODES / GBM), 256>>>(
        node_features, emb_w, emb_b, nullptr, ph, N_NODES, DMODEL, D_IN);

    for (int l = 0; l < NLAYER; l++) {
        // qkv = h @ in_proj^T + b
        tgemm2_kernel<0><<<dim3(3 * DMODEL / GBN, N_NODES / GBM), 256>>>(
            ph, in_proj_w + (size_t)l * 3 * DMODEL * DMODEL,
            in_proj_b + (size_t)l * 3 * DMODEL, nullptr, pqkv,
            N_NODES, 3 * DMODEL, DMODEL);

        // ragged per-graph attention
        attn3_kernel<<<dim3(B_GRAPHS, NHEAD), 256>>>(pqkv, po);

        // x = h + o @ out_w^T + b ; then LN1
        tgemm2_kernel<0><<<dim3(DMODEL / GBN, N_NODES / GBM), 256>>>(
            po, out_w + (size_t)l * DMODEL * DMODEL,
            out_b + (size_t)l * DMODEL, ph, px, N_NODES, DMODEL, DMODEL);
        ln_kernel<<<N_NODES / 8, 256>>>(px, ln1_g + (size_t)l * DMODEL,
                                        ln1_b + (size_t)l * DMODEL);

        // f = relu(x @ w1^T + b1)
        tgemm2_kernel<1><<<dim3(DFF / GBN, N_NODES / GBM), 256>>>(
            px, ffn_w1 + (size_t)l * DFF * DMODEL,
            ffn_b1 + (size_t)l * DFF, nullptr, pf, N_NODES, DFF, DMODEL);

        // h = x + f @ w2^T + b2 ; then LN2
        tgemm2_kernel<0><<<dim3(DMODEL / GBN, N_NODES / GBM), 256>>>(
            pf, ffn_w2 + (size_t)l * DMODEL * DFF,
            ffn_b2 + (size_t)l * DMODEL, px, ph, N_NODES, DMODEL, DFF);
        ln_kernel<<<N_NODES / 8, 256>>>(ph, ln2_g + (size_t)l * DMODEL,
                                        ln2_b + (size_t)l * DMODEL);
    }

    // segment mean pool -> head
    pool_kernel<<<B_GRAPHS, DMODEL>>>(ph, ppool);
    tgemm2_kernel<2><<<dim3(DMODEL / GBN, B_GRAPHS / GBM), 256>>>(
        ppool, head_w1, head_b1, nullptr, pph, B_GRAPHS, DMODEL, DMODEL);
    head2_kernel<<<B_GRAPHS, 32>>>(pph, head_w2, head_b2, out);
}

// round 6
// speedup vs baseline: 1.8056x; 1.8056x over previous
#include <cuda_runtime.h>
#include <math.h>
#include <stdint.h>

#define N_NODES 24576
#define B_GRAPHS 128
#define D_IN     92
#define DMODEL   512
#define NHEAD    8
#define HDIM     64
#define NLAYER   3
#define DFF      2048

// ---------------- device scratch ----------------
__device__ float g_h   [(size_t)N_NODES * DMODEL];
__device__ float g_qkv [(size_t)N_NODES * 3 * DMODEL];
__device__ float g_o   [(size_t)N_NODES * DMODEL];
__device__ float g_x   [(size_t)N_NODES * DMODEL];
__device__ float g_f   [(size_t)N_NODES * DFF];
__device__ float g_pool[B_GRAPHS * DMODEL];
__device__ float g_ph  [B_GRAPHS * DMODEL];
__device__ int   g_counts[B_GRAPHS];
__device__ int   g_starts[B_GRAPHS];

// ---------------- graph metadata ----------------
__global__ void count_kernel(const int* __restrict__ batch) {
    int i = blockIdx.x * blockDim.x + threadIdx.x;
    if (i < N_NODES) {
        int g = batch[i];
        if (g >= 0 && g < B_GRAPHS) atomicAdd(&g_counts[g], 1);
    }
}

__global__ void scan_kernel() {
    int s = 0;
    for (int g = 0; g < B_GRAPHS; g++) {
        g_starts[g] = s;
        s += g_counts[g];
    }
}

// ---------------- tf32 helpers ----------------
__device__ __forceinline__ uint32_t f2tf(float x) {
    uint32_t y;
    asm("cvt.rna.tf32.f32 %0, %1;" : "=r"(y) : "f"(x));
    return y;
}

__device__ __forceinline__ void mma_tf32(float d[4], const uint32_t a[4], const uint32_t b[2]) {
    asm volatile(
        "mma.sync.aligned.m16n8k8.row.col.f32.tf32.tf32.f32 "
        "{%0,%1,%2,%3}, {%4,%5,%6,%7}, {%8,%9}, {%0,%1,%2,%3};\n"
        : "+f"(d[0]), "+f"(d[1]), "+f"(d[2]), "+f"(d[3])
        : "r"(a[0]), "r"(a[1]), "r"(a[2]), "r"(a[3]),
          "r"(b[0]), "r"(b[1]));
}

// ---------------- TF32 GEMM (R4, measured-good):  C = A @ W^T + bias (+res) (+act) ----------------
// 128x128 block tile, BK=16, 8 warps (2m x 4n), warp tile 64x32, double-buffered.
#define TBM 128
#define TBN 128
#define TBK 16
#define KST 20   // smem row stride in uint32 (16 + 4 pad): conflict-free frag loads

template <int ACT>
__global__ void __launch_bounds__(256, 2)
tgemm_kernel(const float* __restrict__ A, const float* __restrict__ W,
             const float* __restrict__ bias, const float* __restrict__ res,
             float* __restrict__ C, int M, int N, int K)
{
    __shared__ uint32_t As[2][TBM][KST];
    __shared__ uint32_t Bs[2][TBN][KST];

    const int tid  = threadIdx.x;
    const int lane = tid & 31;
    const int wid  = tid >> 5;
    const int mw   = wid >> 2;     // 0..1
    const int nw   = wid & 3;      // 0..3
    const int bm = blockIdx.y * TBM;
    const int bn = blockIdx.x * TBN;
    const int wm = mw * 64;
    const int wn = nw * 32;

    const int r0 = tid >> 2;          // 0..63
    const int c4 = (tid & 3) * 4;     // 0,4,8,12

    float acc[4][4][4];
#pragma unroll
    for (int a = 0; a < 4; a++)
#pragma unroll
        for (int b = 0; b < 4; b++)
#pragma unroll
            for (int c = 0; c < 4; c++) acc[a][b][c] = 0.f;

    const int ntiles = (K + TBK - 1) / TBK;

    uint4 pa0, pa1, pb0, pb1;

    auto ldg4 = [&](const float* __restrict__ P, int row, int k, uint4& o4) {
        if (k + 3 < K) {
            float4 f = *(const float4*)(P + (size_t)row * K + k);
            o4.x = f2tf(f.x); o4.y = f2tf(f.y); o4.z = f2tf(f.z); o4.w = f2tf(f.w);
        } else {
            o4 = make_uint4(0u, 0u, 0u, 0u);
        }
    };

    // prologue: tile 0
    ldg4(A, bm + r0,      c4, pa0);
    ldg4(A, bm + r0 + 64, c4, pa1);
    ldg4(W, bn + r0,      c4, pb0);
    ldg4(W, bn + r0 + 64, c4, pb1);
    *(uint4*)&As[0][r0][c4]      = pa0;
    *(uint4*)&As[0][r0 + 64][c4] = pa1;
    *(uint4*)&Bs[0][r0][c4]      = pb0;
    *(uint4*)&Bs[0][r0 + 64][c4] = pb1;
    __syncthreads();

    const int fr = lane >> 2;   // 0..7
    const int fc = lane & 3;    // 0..3

    for (int t = 0; t < ntiles; t++) {
        int buf = t & 1;
        if (t + 1 < ntiles) {
            int k = (t + 1) * TBK + c4;
            ldg4(A, bm + r0,      k, pa0);
            ldg4(A, bm + r0 + 64, k, pa1);
            ldg4(W, bn + r0,      k, pb0);
            ldg4(W, bn + r0 + 64, k, pb1);
        }
#pragma unroll
        for (int ks = 0; ks < 2; ks++) {
            int kb = ks * 8;
            uint32_t af[4][4], bf[4][2];
#pragma unroll
            for (int mt = 0; mt < 4; mt++) {
                int mrow = wm + mt * 16 + fr;
                af[mt][0] = As[buf][mrow    ][kb + fc];
                af[mt][1] = As[buf][mrow + 8][kb + fc];
                af[mt][2] = As[buf][mrow    ][kb + fc + 4];
                af[mt][3] = As[buf][mrow + 8][kb + fc + 4];
            }
#pragma unroll
            for (int nt = 0; nt < 4; nt++) {
                int nrow = wn + nt * 8 + fr;
                bf[nt][0] = Bs[buf][nrow][kb + fc];
                bf[nt][1] = Bs[buf][nrow][kb + fc + 4];
            }
#pragma unroll
            for (int mt = 0; mt < 4; mt++)
#pragma unroll
                for (int nt = 0; nt < 4; nt++)
                    mma_tf32(acc[mt][nt], af[mt], bf[nt]);
        }
        if (t + 1 < ntiles) {
            int nb = buf ^ 1;
            *(uint4*)&As[nb][r0][c4]      = pa0;
            *(uint4*)&As[nb][r0 + 64][c4] = pa1;
            *(uint4*)&Bs[nb][r0][c4]      = pb0;
            *(uint4*)&Bs[nb][r0 + 64][c4] = pb1;
            __syncthreads();
        }
    }

    // epilogue
#pragma unroll
    for (int mt = 0; mt < 4; mt++) {
#pragma unroll
        for (int nt = 0; nt < 4; nt++) {
            int col = bn + wn + nt * 8 + 2 * fc;
            float2 bi = *(const float2*)(bias + col);
#pragma unroll
            for (int h = 0; h < 2; h++) {
                int row = bm + wm + mt * 16 + fr + h * 8;
                float v0 = acc[mt][nt][h * 2 + 0] + bi.x;
                float v1 = acc[mt][nt][h * 2 + 1] + bi.y;
                if (res) {
                    float2 rr = *(const float2*)(res + (size_t)row * N + col);
                    v0 += rr.x; v1 += rr.y;
                }
                if (ACT == 1) { v0 = fmaxf(v0, 0.f); v1 = fmaxf(v1, 0.f); }
                if (ACT == 2) { v0 = v0 / (1.f + expf(-v0)); v1 = v1 / (1.f + expf(-v1)); }
                *(float2*)(C + (size_t)row * N + col) = make_float2(v0, v1);
            }
        }
    }
}

// ---------------- attention v3: block per (graph, head), 32 queries/stage ----------------
__global__ void __launch_bounds__(256)
attn3_kernel(const float* __restrict__ qkv, float* __restrict__ o)
{
    __shared__ float Ks[32][65];
    __shared__ float Vs[32][64];
    __shared__ float qs[32][64];

    const int g = blockIdx.x, head = blockIdx.y;
    const int s0 = g_starts[g], cnt = g_counts[g];
    const int tid = threadIdx.x, lane = tid & 31, wid = tid >> 5;
    const float scale = 0.125f;   // 1/sqrt(64)

    for (int qg = 0; qg < cnt; qg += 32) {
        int nq = min(32, cnt - qg);
        __syncthreads();
        // stage up to 32 query rows (pre-scaled)
        for (int i = tid; i < nq * 16; i += 256) {
            int r = i >> 4, c = (i & 15) * 4;
            const float* qr = qkv + (size_t)(s0 + qg + r) * (3 * DMODEL) + head * HDIM;
            float4 qf = *(const float4*)(qr + c);
            qs[r][c]     = qf.x * scale;
            qs[r][c + 1] = qf.y * scale;
            qs[r][c + 2] = qf.z * scale;
            qs[r][c + 3] = qf.w * scale;
        }
        __syncthreads();

        // per-warp: 4 query states (queries wid + 8*j)
        float m[4], l[4], a0[4], a1[4];
#pragma unroll
        for (int j = 0; j < 4; j++) { m[j] = -1e30f; l[j] = 0.f; a0[j] = 0.f; a1[j] = 0.f; }

        for (int t0 = 0; t0 < cnt; t0 += 32) {
            int nk = min(32, cnt - t0);
            __syncthreads();
            for (int i = tid; i < nk * 16; i += 256) {
                int r = i >> 4, c = (i & 15) * 4;
                const float* kr = qkv + (size_t)(s0 + t0 + r) * (3 * DMODEL) + DMODEL + head * HDIM;
                float4 kf = *(const float4*)(kr + c);
                float4 vf = *(const float4*)(kr + DMODEL + c);
                Ks[r][c] = kf.x; Ks[r][c + 1] = kf.y; Ks[r][c + 2] = kf.z; Ks[r][c + 3] = kf.w;
                *(float4*)&Vs[r][c] = vf;
            }
            __syncthreads();

#pragma unroll
            for (int j = 0; j < 4; j++) {
                int qi = wid + 8 * j;
                if (qi >= nq) break;
                float s = -1e30f;
                if (lane < nk) {
                    float p0 = 0.f, p1 = 0.f, p2 = 0.f, p3 = 0.f;
#pragma unroll 8
                    for (int d = 0; d < 64; d += 4) {
                        p0 += qs[qi][d]     * Ks[lane][d];
                        p1 += qs[qi][d + 1] * Ks[lane][d + 1];
                        p2 += qs[qi][d + 2] * Ks[lane][d + 2];
                        p3 += qs[qi][d + 3] * Ks[lane][d + 3];
                    }
                    s = (p0 + p1) + (p2 + p3);
                }
                float tm = s;
#pragma unroll
                for (int off = 16; off; off >>= 1)
                    tm = fmaxf(tm, __shfl_xor_sync(0xffffffffu, tm, off));
                float nm = fmaxf(m[j], tm);
                float corr = expf(m[j] - nm);
                float e = (lane < nk) ? expf(s - nm) : 0.f;
                float es = e;
#pragma unroll
                for (int off = 16; off; off >>= 1)
                    es += __shfl_xor_sync(0xffffffffu, es, off);
                l[j] = l[j] * corr + es;
                a0[j] *= corr; a1[j] *= corr;
                for (int kk = 0; kk < nk; kk++) {
                    float w = __shfl_sync(0xffffffffu, e, kk);
                    a0[j] += w * Vs[kk][lane];
                    a1[j] += w * Vs[kk][lane + 32];
                }
                m[j] = nm;
            }
        }

#pragma unroll
        for (int j = 0; j < 4; j++) {
            int qi = wid + 8 * j;
            if (qi >= nq) break;
            float inv = 1.f / l[j];
            float* orow = o + (size_t)(s0 + qg + qi) * DMODEL + head * HDIM;
            orow[lane]      = a0[j] * inv;
            orow[lane + 32] = a1[j] * inv;
        }
    }
}

// ---------------- layernorm (in-place), one warp per row ----------------
__global__ void ln_kernel(float* __restrict__ x,
                          const float* __restrict__ gamma,
                          const float* __restrict__ beta)
{
    int row  = (blockIdx.x * blockDim.x + threadIdx.x) >> 5;
    int lane = threadIdx.x & 31;
    if (row >= N_NODES) return;
    float* xr = x + (size_t)row * DMODEL;

    float v[16];
    float s = 0.f;
#pragma unroll
    for (int i = 0; i < 16; i++) { v[i] = xr[i * 32 + lane]; s += v[i]; }
#pragma unroll
    for (int off = 16; off; off >>= 1) s += __shfl_xor_sync(0xffffffffu, s, off);
    float mu = s * (1.f / DMODEL);

    float s2 = 0.f;
#pragma unroll
    for (int i = 0; i < 16; i++) { float d = v[i] - mu; v[i] = d; s2 += d * d; }
#pragma unroll
    for (int off = 16; off; off >>= 1) s2 += __shfl_xor_sync(0xffffffffu, s2, off);
    float rstd = rsqrtf(s2 * (1.f / DMODEL) + 1e-5f);

#pragma unroll
    for (int i = 0; i < 16; i++) {
        int c = i * 32 + lane;
        xr[c] = v[i] * rstd * gamma[c] + beta[c];
    }
}

// ---------------- segment mean pool ----------------
__global__ void pool_kernel(const float* __restrict__ h, float* __restrict__ pooled)
{
    int g = blockIdx.x;
    int d = threadIdx.x;   // 512 threads
    int s0 = g_starts[g];
    int c  = g_counts[g];
    float acc = 0.f;
    for (int j = 0; j < c; j++) acc += h[(size_t)(s0 + j) * DMODEL + d];
    pooled[g * DMODEL + d] = (c > 0) ? acc / (float)c : 0.f;
}

// ---------------- final head ----------------
__global__ void head2_kernel(const float* __restrict__ ph,
                             const float* __restrict__ w2,
                             const float* __restrict__ b2,
                             float* __restrict__ out)
{
    int g = blockIdx.x;
    int lane = threadIdx.x;
    float acc = 0.f;
    for (int i = lane; i < DMODEL; i += 32) acc += ph[g * DMODEL + i] * w2[i];
#pragma unroll
    for (int off = 16; off; off >>= 1) acc += __shfl_xor_sync(0xffffffffu, acc, off);
    if (lane == 0) out[g] = acc + b2[0];
}

// ---------------- host orchestration ----------------
extern "C" void kernel_launch(void* const* d_in, const int* in_sizes, int n_in,
                              void* d_out, int out_size)
{
    const float* node_features = (const float*)d_in[0];
    const int*   batch         = (const int*)  d_in[3];
    const float* emb_w   = (const float*)d_in[4];
    const float* emb_b   = (const float*)d_in[5];
    const float* in_proj_w = (const float*)d_in[6];
    const float* in_proj_b = (const float*)d_in[7];
    const float* out_w   = (const float*)d_in[8];
    const float* out_b   = (const float*)d_in[9];
    const float* ln1_g   = (const float*)d_in[10];
    const float* ln1_b   = (const float*)d_in[11];
    const float* ffn_w1  = (const float*)d_in[12];
    const float* ffn_b1  = (const float*)d_in[13];
    const float* ffn_w2  = (const float*)d_in[14];
    const float* ffn_b2  = (const float*)d_in[15];
    const float* ln2_g   = (const float*)d_in[16];
    const float* ln2_b   = (const float*)d_in[17];
    const float* head_w1 = (const float*)d_in[18];
    const float* head_b1 = (const float*)d_in[19];
    const float* head_w2 = (const float*)d_in[20];
    const float* head_b2 = (const float*)d_in[21];
    float* out = (float*)d_out;

    float *ph, *pqkv, *po, *px, *pf, *ppool, *pph;
    int *pcounts;
    cudaGetSymbolAddress((void**)&ph,     g_h);
    cudaGetSymbolAddress((void**)&pqkv,   g_qkv);
    cudaGetSymbolAddress((void**)&po,     g_o);
    cudaGetSymbolAddress((void**)&px,     g_x);
    cudaGetSymbolAddress((void**)&pf,     g_f);
    cudaGetSymbolAddress((void**)&ppool,  g_pool);
    cudaGetSymbolAddress((void**)&pph,    g_ph);
    cudaGetSymbolAddress((void**)&pcounts, g_counts);

    // graph metadata
    cudaMemsetAsync(pcounts, 0, B_GRAPHS * sizeof(int));
    count_kernel<<<(N_NODES + 255) / 256, 256>>>(batch);
    scan_kernel<<<1, 1>>>();

    // embedding: h = X @ emb_w^T + emb_b
    tgemm_kernel<0><<<dim3(DMODEL / TBN, N_NODES / TBM), 256>>>(
        node_features, emb_w, emb_b, nullptr, ph, N_NODES, DMODEL, D_IN);

    for (int l = 0; l < NLAYER; l++) {
        // qkv = h @ in_proj^T + b
        tgemm_kernel<0><<<dim3(3 * DMODEL / TBN, N_NODES / TBM), 256>>>(
            ph, in_proj_w + (size_t)l * 3 * DMODEL * DMODEL,
            in_proj_b + (size_t)l * 3 * DMODEL, nullptr, pqkv,
            N_NODES, 3 * DMODEL, DMODEL);

        // ragged per-graph attention
        attn3_kernel<<<dim3(B_GRAPHS, NHEAD), 256>>>(pqkv, po);

        // x = h + o @ out_w^T + b ; then LN1
        tgemm_kernel<0><<<dim3(DMODEL / TBN, N_NODES / TBM), 256>>>(
            po, out_w + (size_t)l * DMODEL * DMODEL,
            out_b + (size_t)l * DMODEL, ph, px, N_NODES, DMODEL, DMODEL);
        ln_kernel<<<N_NODES / 8, 256>>>(px, ln1_g + (size_t)l * DMODEL,
                                        ln1_b + (size_t)l * DMODEL);

        // f = relu(x @ w1^T + b1)
        tgemm_kernel<1><<<dim3(DFF / TBN, N_NODES / TBM), 256>>>(
            px, ffn_w1 + (size_t)l * DFF * DMODEL,
            ffn_b1 + (size_t)l * DFF, nullptr, pf, N_NODES, DFF, DMODEL);

        // h = x + f @ w2^T + b2 ; then LN2
        tgemm_kernel<0><<<dim3(DMODEL / TBN, N_NODES / TBM), 256>>>(
            pf, ffn_w2 + (size_t)l * DMODEL * DFF,
            ffn_b2 + (size_t)l * DMODEL, px, ph, N_NODES, DMODEL, DFF);
        ln_kernel<<<N_NODES / 8, 256>>>(ph, ln2_g + (size_t)l * DMODEL,
                                        ln2_b + (size_t)l * DMODEL);
    }

    // segment mean pool -> head
    pool_kernel<<<B_GRAPHS, DMODEL>>>(ph, ppool);
    tgemm_kernel<2><<<dim3(DMODEL / TBN, B_GRAPHS / TBM), 256>>>(
        ppool, head_w1, head_b1, nullptr, pph, B_GRAPHS, DMODEL, DMODEL);
    head2_kernel<<<B_GRAPHS, 32>>>(pph, head_w2, head_b2, out);
}

// round 7
// speedup vs baseline: 1.8691x; 1.0352x over previous
#include <cuda_runtime.h>
#include <math.h>
#include <stdint.h>

#define N_NODES 24576
#define B_GRAPHS 128
#define D_IN     92
#define DMODEL   512
#define NHEAD    8
#define HDIM     64
#define NLAYER   3
#define DFF      2048

// ---------------- device scratch ----------------
__device__ float g_h   [(size_t)N_NODES * DMODEL];
__device__ float g_qkv [(size_t)N_NODES * 3 * DMODEL];
__device__ float g_o   [(size_t)N_NODES * DMODEL];
__device__ float g_x   [(size_t)N_NODES * DMODEL];
__device__ float g_f   [(size_t)N_NODES * DFF];
__device__ float g_pool[B_GRAPHS * DMODEL];
__device__ float g_ph  [B_GRAPHS * DMODEL];
__device__ int   g_counts[B_GRAPHS];
__device__ int   g_starts[B_GRAPHS];

// ---------------- graph metadata ----------------
__global__ void count_kernel(const int* __restrict__ batch) {
    int i = blockIdx.x * blockDim.x + threadIdx.x;
    if (i < N_NODES) {
        int g = batch[i];
        if (g >= 0 && g < B_GRAPHS) atomicAdd(&g_counts[g], 1);
    }
}

__global__ void scan_kernel() {
    int s = 0;
    for (int g = 0; g < B_GRAPHS; g++) {
        g_starts[g] = s;
        s += g_counts[g];
    }
}

// ---------------- tf32 helpers ----------------
__device__ __forceinline__ uint32_t f2tf(float x) {
    uint32_t y;
    asm("cvt.rna.tf32.f32 %0, %1;" : "=r"(y) : "f"(x));
    return y;
}
__device__ __forceinline__ uint32_t u2tf(uint32_t w) {
    return f2tf(__uint_as_float(w));
}

__device__ __forceinline__ void mma_tf32(float d[4], const uint32_t a[4], const uint32_t b[2]) {
    asm volatile(
        "mma.sync.aligned.m16n8k8.row.col.f32.tf32.tf32.f32 "
        "{%0,%1,%2,%3}, {%4,%5,%6,%7}, {%8,%9}, {%0,%1,%2,%3};\n"
        : "+f"(d[0]), "+f"(d[1]), "+f"(d[2]), "+f"(d[3])
        : "r"(a[0]), "r"(a[1]), "r"(a[2]), "r"(a[3]),
          "r"(b[0]), "r"(b[1]));
}

__device__ __forceinline__ void cp16(uint32_t dst_smem, const void* src) {
    asm volatile("cp.async.cg.shared.global [%0], [%1], 16;\n"
                 :: "r"(dst_smem), "l"(src));
}

// ---------------- TF32 GEMM v3: cp.async 4-stage pipeline ----------------
// C = A @ W^T + bias (+res) (+act). A: MxK, W: NxK row-major fp32.
// M % 128 == 0, N % 128 == 0, K % 4 == 0. 128x128 tile, BK=16, 8 warps, 64x32 warp tile.
#define TBM 128
#define TBN 128
#define TBK 16
#define KST 20   // smem row stride in u32 (16+4 pad); 80B rows keep 16B alignment
#define NS  4    // pipeline stages
#define TG_SMEM_BYTES (2 * NS * TBM * KST * 4)   // 80 KB

template <int ACT>
__global__ void __launch_bounds__(256, 2)
tgemm3_kernel(const float* __restrict__ A, const float* __restrict__ W,
              const float* __restrict__ bias, const float* __restrict__ res,
              float* __restrict__ C, int M, int N, int K)
{
    extern __shared__ uint32_t smem[];
    uint32_t (*As)[TBM][KST] = (uint32_t (*)[TBM][KST])smem;
    uint32_t (*Bs)[TBM][KST] = (uint32_t (*)[TBM][KST])(smem + NS * TBM * KST);

    const int tid  = threadIdx.x;
    const int lane = tid & 31;
    const int wid  = tid >> 5;
    const int mw   = wid >> 2;     // 0..1
    const int nw   = wid & 3;      // 0..3
    const int bm = blockIdx.y * TBM;
    const int bn = blockIdx.x * TBN;
    const int wm = mw * 64;
    const int wn = nw * 32;

    const int r0 = tid >> 2;          // 0..63
    const int c4 = (tid & 3) * 4;     // 0,4,8,12

    const uint32_t sA = (uint32_t)__cvta_generic_to_shared(smem);
    const uint32_t sB = sA + NS * TBM * KST * 4;

    float acc[4][4][4];
#pragma unroll
    for (int a = 0; a < 4; a++)
#pragma unroll
        for (int b = 0; b < 4; b++)
#pragma unroll
            for (int c = 0; c < 4; c++) acc[a][b][c] = 0.f;

    const int ntiles = (K + TBK - 1) / TBK;

    auto copy_tile = [&](int t) {
        int s = t % NS;
        int k = t * TBK + c4;
        uint32_t da0 = sA + (((s * TBM) + r0)      * KST + c4) * 4;
        uint32_t da1 = sA + (((s * TBM) + r0 + 64) * KST + c4) * 4;
        uint32_t db0 = sB + (((s * TBM) + r0)      * KST + c4) * 4;
        uint32_t db1 = sB + (((s * TBM) + r0 + 64) * KST + c4) * 4;
        if (k + 4 <= K) {
            cp16(da0, A + (size_t)(bm + r0)      * K + k);
            cp16(da1, A + (size_t)(bm + r0 + 64) * K + k);
            cp16(db0, W + (size_t)(bn + r0)      * K + k);
            cp16(db1, W + (size_t)(bn + r0 + 64) * K + k);
        } else {
            // boundary chunk (embed K=92): zero-fill via regular stores
#pragma unroll
            for (int i = 0; i < 4; i++) {
                As[s][r0][c4 + i]      = 0u;
                As[s][r0 + 64][c4 + i] = 0u;
                Bs[s][r0][c4 + i]      = 0u;
                Bs[s][r0 + 64][c4 + i] = 0u;
            }
        }
    };

    // prologue: stages 0..NS-2
#pragma unroll
    for (int t = 0; t < NS - 1; t++) {
        if (t < ntiles) copy_tile(t);
        asm volatile("cp.async.commit_group;\n");
    }

    const int fr = lane >> 2;   // 0..7
    const int fc = lane & 3;    // 0..3

    for (int t = 0; t < ntiles; t++) {
        asm volatile("cp.async.wait_group %0;\n" :: "n"(NS - 2));
        __syncthreads();
        if (t + NS - 1 < ntiles) copy_tile(t + NS - 1);
        asm volatile("cp.async.commit_group;\n");

        const int s = t % NS;
#pragma unroll
        for (int ks = 0; ks < 2; ks++) {
            int kb = ks * 8;
            uint32_t af[4][4], bf[4][2];
#pragma unroll
            for (int mt = 0; mt < 4; mt++) {
                int mrow = wm + mt * 16 + fr;
                af[mt][0] = u2tf(As[s][mrow    ][kb + fc]);
                af[mt][1] = u2tf(As[s][mrow + 8][kb + fc]);
                af[mt][2] = u2tf(As[s][mrow    ][kb + fc + 4]);
                af[mt][3] = u2tf(As[s][mrow + 8][kb + fc + 4]);
            }
#pragma unroll
            for (int nt = 0; nt < 4; nt++) {
                int nrow = wn + nt * 8 + fr;
                bf[nt][0] = u2tf(Bs[s][nrow][kb + fc]);
                bf[nt][1] = u2tf(Bs[s][nrow][kb + fc + 4]);
            }
#pragma unroll
            for (int mt = 0; mt < 4; mt++)
#pragma unroll
                for (int nt = 0; nt < 4; nt++)
                    mma_tf32(acc[mt][nt], af[mt], bf[nt]);
        }
    }

    // epilogue
#pragma unroll
    for (int mt = 0; mt < 4; mt++) {
#pragma unroll
        for (int nt = 0; nt < 4; nt++) {
            int col = bn + wn + nt * 8 + 2 * fc;
            float2 bi = *(const float2*)(bias + col);
#pragma unroll
            for (int h = 0; h < 2; h++) {
                int row = bm + wm + mt * 16 + fr + h * 8;
                float v0 = acc[mt][nt][h * 2 + 0] + bi.x;
                float v1 = acc[mt][nt][h * 2 + 1] + bi.y;
                if (res) {
                    float2 rr = *(const float2*)(res + (size_t)row * N + col);
                    v0 += rr.x; v1 += rr.y;
                }
                if (ACT == 1) { v0 = fmaxf(v0, 0.f); v1 = fmaxf(v1, 0.f); }
                if (ACT == 2) { v0 = v0 / (1.f + expf(-v0)); v1 = v1 / (1.f + expf(-v1)); }
                *(float2*)(C + (size_t)row * N + col) = make_float2(v0, v1);
            }
        }
    }
}

// ---------------- attention v3: block per (graph, head), 32 queries/stage ----------------
__global__ void __launch_bounds__(256)
attn3_kernel(const float* __restrict__ qkv, float* __restrict__ o)
{
    __shared__ float Ks[32][65];
    __shared__ float Vs[32][64];
    __shared__ float qs[32][64];

    const int g = blockIdx.x, head = blockIdx.y;
    const int s0 = g_starts[g], cnt = g_counts[g];
    const int tid = threadIdx.x, lane = tid & 31, wid = tid >> 5;
    const float scale = 0.125f;   // 1/sqrt(64)

    for (int qg = 0; qg < cnt; qg += 32) {
        int nq = min(32, cnt - qg);
        __syncthreads();
        for (int i = tid; i < nq * 16; i += 256) {
            int r = i >> 4, c = (i & 15) * 4;
            const float* qr = qkv + (size_t)(s0 + qg + r) * (3 * DMODEL) + head * HDIM;
            float4 qf = *(const float4*)(qr + c);
            qs[r][c]     = qf.x * scale;
            qs[r][c + 1] = qf.y * scale;
            qs[r][c + 2] = qf.z * scale;
            qs[r][c + 3] = qf.w * scale;
        }
        __syncthreads();

        float m[4], l[4], a0[4], a1[4];
#pragma unroll
        for (int j = 0; j < 4; j++) { m[j] = -1e30f; l[j] = 0.f; a0[j] = 0.f; a1[j] = 0.f; }

        for (int t0 = 0; t0 < cnt; t0 += 32) {
            int nk = min(32, cnt - t0);
            __syncthreads();
            for (int i = tid; i < nk * 16; i += 256) {
                int r = i >> 4, c = (i & 15) * 4;
                const float* kr = qkv + (size_t)(s0 + t0 + r) * (3 * DMODEL) + DMODEL + head * HDIM;
                float4 kf = *(const float4*)(kr + c);
                float4 vf = *(const float4*)(kr + DMODEL + c);
                Ks[r][c] = kf.x; Ks[r][c + 1] = kf.y; Ks[r][c + 2] = kf.z; Ks[r][c + 3] = kf.w;
                *(float4*)&Vs[r][c] = vf;
            }
            __syncthreads();

#pragma unroll
            for (int j = 0; j < 4; j++) {
                int qi = wid + 8 * j;
                if (qi >= nq) break;
                float s = -1e30f;
                if (lane < nk) {
                    float p0 = 0.f, p1 = 0.f, p2 = 0.f, p3 = 0.f;
#pragma unroll 8
                    for (int d = 0; d < 64; d += 4) {
                        p0 += qs[qi][d]     * Ks[lane][d];
                        p1 += qs[qi][d + 1] * Ks[lane][d + 1];
                        p2 += qs[qi][d + 2] * Ks[lane][d + 2];
                        p3 += qs[qi][d + 3] * Ks[lane][d + 3];
                    }
                    s = (p0 + p1) + (p2 + p3);
                }
                float tm = s;
#pragma unroll
                for (int off = 16; off; off >>= 1)
                    tm = fmaxf(tm, __shfl_xor_sync(0xffffffffu, tm, off));
                float nm = fmaxf(m[j], tm);
                float corr = expf(m[j] - nm);
                float e = (lane < nk) ? expf(s - nm) : 0.f;
                float es = e;
#pragma unroll
                for (int off = 16; off; off >>= 1)
                    es += __shfl_xor_sync(0xffffffffu, es, off);
                l[j] = l[j] * corr + es;
                a0[j] *= corr; a1[j] *= corr;
                for (int kk = 0; kk < nk; kk++) {
                    float w = __shfl_sync(0xffffffffu, e, kk);
                    a0[j] += w * Vs[kk][lane];
                    a1[j] += w * Vs[kk][lane + 32];
                }
                m[j] = nm;
            }
        }

#pragma unroll
        for (int j = 0; j < 4; j++) {
            int qi = wid + 8 * j;
            if (qi >= nq) break;
            float inv = 1.f / l[j];
            float* orow = o + (size_t)(s0 + qg + qi) * DMODEL + head * HDIM;
            orow[lane]      = a0[j] * inv;
            orow[lane + 32] = a1[j] * inv;
        }
    }
}

// ---------------- layernorm (in-place), one warp per row ----------------
__global__ void ln_kernel(float* __restrict__ x,
                          const float* __restrict__ gamma,
                          const float* __restrict__ beta)
{
    int row  = (blockIdx.x * blockDim.x + threadIdx.x) >> 5;
    int lane = threadIdx.x & 31;
    if (row >= N_NODES) return;
    float* xr = x + (size_t)row * DMODEL;

    float v[16];
    float s = 0.f;
#pragma unroll
    for (int i = 0; i < 16; i++) { v[i] = xr[i * 32 + lane]; s += v[i]; }
#pragma unroll
    for (int off = 16; off; off >>= 1) s += __shfl_xor_sync(0xffffffffu, s, off);
    float mu = s * (1.f / DMODEL);

    float s2 = 0.f;
#pragma unroll
    for (int i = 0; i < 16; i++) { float d = v[i] - mu; v[i] = d; s2 += d * d; }
#pragma unroll
    for (int off = 16; off; off >>= 1) s2 += __shfl_xor_sync(0xffffffffu, s2, off);
    float rstd = rsqrtf(s2 * (1.f / DMODEL) + 1e-5f);

#pragma unroll
    for (int i = 0; i < 16; i++) {
        int c = i * 32 + lane;
        xr[c] = v[i] * rstd * gamma[c] + beta[c];
    }
}

// ---------------- segment mean pool ----------------
__global__ void pool_kernel(const float* __restrict__ h, float* __restrict__ pooled)
{
    int g = blockIdx.x;
    int d = threadIdx.x;   // 512 threads
    int s0 = g_starts[g];
    int c  = g_counts[g];
    float acc = 0.f;
    for (int j = 0; j < c; j++) acc += h[(size_t)(s0 + j) * DMODEL + d];
    pooled[g * DMODEL + d] = (c > 0) ? acc / (float)c : 0.f;
}

// ---------------- final head ----------------
__global__ void head2_kernel(const float* __restrict__ ph,
                             const float* __restrict__ w2,
                             const float* __restrict__ b2,
                             float* __restrict__ out)
{
    int g = blockIdx.x;
    int lane = threadIdx.x;
    float acc = 0.f;
    for (int i = lane; i < DMODEL; i += 32) acc += ph[g * DMODEL + i] * w2[i];
#pragma unroll
    for (int off = 16; off; off >>= 1) acc += __shfl_xor_sync(0xffffffffu, acc, off);
    if (lane == 0) out[g] = acc + b2[0];
}

// ---------------- host orchestration ----------------
extern "C" void kernel_launch(void* const* d_in, const int* in_sizes, int n_in,
                              void* d_out, int out_size)
{
    const float* node_features = (const float*)d_in[0];
    const int*   batch         = (const int*)  d_in[3];
    const float* emb_w   = (const float*)d_in[4];
    const float* emb_b   = (const float*)d_in[5];
    const float* in_proj_w = (const float*)d_in[6];
    const float* in_proj_b = (const float*)d_in[7];
    const float* out_w   = (const float*)d_in[8];
    const float* out_b   = (const float*)d_in[9];
    const float* ln1_g   = (const float*)d_in[10];
    const float* ln1_b   = (const float*)d_in[11];
    const float* ffn_w1  = (const float*)d_in[12];
    const float* ffn_b1  = (const float*)d_in[13];
    const float* ffn_w2  = (const float*)d_in[14];
    const float* ffn_b2  = (const float*)d_in[15];
    const float* ln2_g   = (const float*)d_in[16];
    const float* ln2_b   = (const float*)d_in[17];
    const float* head_w1 = (const float*)d_in[18];
    const float* head_b1 = (const float*)d_in[19];
    const float* head_w2 = (const float*)d_in[20];
    const float* head_b2 = (const float*)d_in[21];
    float* out = (float*)d_out;

    float *ph, *pqkv, *po, *px, *pf, *ppool, *pph;
    int *pcounts;
    cudaGetSymbolAddress((void**)&ph,     g_h);
    cudaGetSymbolAddress((void**)&pqkv,   g_qkv);
    cudaGetSymbolAddress((void**)&po,     g_o);
    cudaGetSymbolAddress((void**)&px,     g_x);
    cudaGetSymbolAddress((void**)&pf,     g_f);
    cudaGetSymbolAddress((void**)&ppool,  g_pool);
    cudaGetSymbolAddress((void**)&pph,    g_ph);
    cudaGetSymbolAddress((void**)&pcounts, g_counts);

    // allow 80KB dynamic smem for the pipelined GEMM (idempotent)
    cudaFuncSetAttribute(tgemm3_kernel<0>, cudaFuncAttributeMaxDynamicSharedMemorySize, TG_SMEM_BYTES);
    cudaFuncSetAttribute(tgemm3_kernel<1>, cudaFuncAttributeMaxDynamicSharedMemorySize, TG_SMEM_BYTES);
    cudaFuncSetAttribute(tgemm3_kernel<2>, cudaFuncAttributeMaxDynamicSharedMemorySize, TG_SMEM_BYTES);

    // graph metadata
    cudaMemsetAsync(pcounts, 0, B_GRAPHS * sizeof(int));
    count_kernel<<<(N_NODES + 255) / 256, 256>>>(batch);
    scan_kernel<<<1, 1>>>();

    // embedding: h = X @ emb_w^T + emb_b
    tgemm3_kernel<0><<<dim3(DMODEL / TBN, N_NODES / TBM), 256, TG_SMEM_BYTES>>>(
        node_features, emb_w, emb_b, nullptr, ph, N_NODES, DMODEL, D_IN);

    for (int l = 0; l < NLAYER; l++) {
        // qkv = h @ in_proj^T + b
        tgemm3_kernel<0><<<dim3(3 * DMODEL / TBN, N_NODES / TBM), 256, TG_SMEM_BYTES>>>(
            ph, in_proj_w + (size_t)l * 3 * DMODEL * DMODEL,
            in_proj_b + (size_t)l * 3 * DMODEL, nullptr, pqkv,
            N_NODES, 3 * DMODEL, DMODEL);

        // ragged per-graph attention
        attn3_kernel<<<dim3(B_GRAPHS, NHEAD), 256>>>(pqkv, po);

        // x = h + o @ out_w^T + b ; then LN1
        tgemm3_kernel<0><<<dim3(DMODEL / TBN, N_NODES / TBM), 256, TG_SMEM_BYTES>>>(
            po, out_w + (size_t)l * DMODEL * DMODEL,
            out_b + (size_t)l * DMODEL, ph, px, N_NODES, DMODEL, DMODEL);
        ln_kernel<<<N_NODES / 8, 256>>>(px, ln1_g + (size_t)l * DMODEL,
                                        ln1_b + (size_t)l * DMODEL);

        // f = relu(x @ w1^T + b1)
        tgemm3_kernel<1><<<dim3(DFF / TBN, N_NODES / TBM), 256, TG_SMEM_BYTES>>>(
            px, ffn_w1 + (size_t)l * DFF * DMODEL,
            ffn_b1 + (size_t)l * DFF, nullptr, pf, N_NODES, DFF, DMODEL);

        // h = x + f @ w2^T + b2 ; then LN2
        tgemm3_kernel<0><<<dim3(DMODEL / TBN, N_NODES / TBM), 256, TG_SMEM_BYTES>>>(
            pf, ffn_w2 + (size_t)l * DMODEL * DFF,
            ffn_b2 + (size_t)l * DMODEL, px, ph, N_NODES, DMODEL, DFF);
        ln_kernel<<<N_NODES / 8, 256>>>(ph, ln2_g + (size_t)l * DMODEL,
                                        ln2_b + (size_t)l * DMODEL);
    }

    // segment mean pool -> head
    pool_kernel<<<B_GRAPHS, DMODEL>>>(ph, ppool);
    tgemm3_kernel<2><<<dim3(DMODEL / TBN, B_GRAPHS / TBM), 256, TG_SMEM_BYTES>>>(
        ppool, head_w1, head_b1, nullptr, pph, B_GRAPHS, DMODEL, DMODEL);
    head2_kernel<<<B_GRAPHS, 32>>>(pph, head_w2, head_b2, out);
}